// round 10
// baseline (speedup 1.0000x reference)
#include <cuda_runtime.h>
#include <cuda_bf16.h>

// QuantumCBOW: B=16384, S=10, DIM=8, TRIL=36.
// R10: two-kernel split.
//  Kernel A (B*11 threads): per-token normalized densities, warp-cooperative
//    gather (4.5x fewer L1tex wavefronts) via conflict-free smem staging;
//    writes mask-weighted densities to __device__ scratch in [slot][v][e]
//    transposed layout (coalesced for kernel B).
//  Kernel B (B threads): coalesced scratch reads -> ctx mean + sigma, then
//    R9's validated Cholesky -> C^T sigma C -> 3-sweep packed Jacobi -> out.

#define QC_DIM  8
#define QC_TRIL 36
#define QC_S    10
#define QC_B    16384
#define SLOTS   11            // 10 context tokens + 1 target

__device__ __forceinline__ constexpr int sidx(int i, int j) { return i * (i + 1) / 2 + j; }
__device__ __forceinline__ constexpr int symi(int i, int j) { return (i >= j) ? sidx(i, j) : sidx(j, i); }

// Scratch: [s][v][e] float4, s in 0..10, v in 0..8, e in 0..QC_B-1. ~25.9MB.
__device__ float4 g_scratch[SLOTS * 9 * QC_B];

// ---------------- Kernel A: per-token densities ----------------
__global__ void __launch_bounds__(32, 8)
density_kernel(const int* __restrict__ contexts,
               const int* __restrict__ targets,
               const float* __restrict__ emb,
               int B) {
    const int t = threadIdx.x;                    // lane
    const int s = blockIdx.y;                     // slot 0..10
    const int e = blockIdx.x * 32 + t;            // batch element
    const bool valid = (e < B);

    // token + mask for this (e, s)
    int tok = 0;
    float m = 0.f;
    if (valid) {
        if (s == QC_S) { tok = targets[e]; m = 1.f; }
        else           { tok = contexts[e * QC_S + s]; m = (tok != 0) ? 1.f : 0.f; }
    }

    // Cooperative load of the warp's 32 rows (32 x 9 float4) into smem.
    // Layout [r*9 + v]: 16B-slot index = 9r+v; 9 odd => lane-distinct mod 8
    // for both the cooperative stores and the per-row loads (conflict-free).
    __shared__ float4 rows[32 * 9];
#pragma unroll
    for (int i = 0; i < 9; i++) {
        const int g = i * 32 + t;                 // 0..287
        const int r = g / 9;                      // source row (lane) 0..31
        const int v = g - r * 9;                  // chunk 0..8
        const int tk = __shfl_sync(0xffffffffu, tok, r);
        rows[g] = *(reinterpret_cast<const float4*>(emb) + (long)tk * 9 + v);
    }
    __syncwarp();

    // Density of my row (lane t) from smem.
    float L[QC_TRIL];
#pragma unroll
    for (int v = 0; v < 9; v++) {
        const float4 q = rows[t * 9 + v];
        L[4 * v + 0] = q.x; L[4 * v + 1] = q.y;
        L[4 * v + 2] = q.z; L[4 * v + 3] = q.w;
    }
#pragma unroll
    for (int i = 0; i < QC_DIM; i++) {
        const int d = sidx(i, i);
        L[d] = fmaxf(L[d], 1e-4f);
    }
    float tr = 0.f;
#pragma unroll
    for (int i = 0; i < QC_TRIL; i++) tr = fmaf(L[i], L[i], tr);
    const float inv = m * __fdividef(1.0f, tr + 1.7e-5f);  // mask folded in

    float o[QC_TRIL];
#pragma unroll
    for (int i = 0; i < QC_DIM; i++) {
#pragma unroll
        for (int j = 0; j <= i; j++) {
            float acc = 0.f;
#pragma unroll
            for (int k = 0; k <= j; k++)
                acc = fmaf(L[sidx(i, k)], L[sidx(j, k)], acc);
            if (i == j) acc += 2e-6f;             // eps + corr
            o[sidx(i, j)] = acc * inv;
        }
    }

    if (valid) {
        float4* scr = g_scratch + (long)s * 9 * QC_B;
#pragma unroll
        for (int v = 0; v < 9; v++)               // coalesced: consecutive e
            scr[v * QC_B + e] = make_float4(o[4 * v], o[4 * v + 1], o[4 * v + 2], o[4 * v + 3]);
    }
}

// ---------------- Kernel B: fidelity ----------------
// Packed-symmetric branchless Jacobi rotation on W[36], pair (p,q), p<q.
#define JROT(p, q) do {                                                        \
    const float apq = W[sidx(q, p)];                                           \
    const float dd  = W[sidx(q, q)] - W[sidx(p, p)];                           \
    const float a2  = 2.0f * apq;                                              \
    const float vv  = fmaf(dd, dd, fmaf(a2, a2, 1e-30f));                      \
    const float u   = vv * rsqrtf(vv);                                         \
    const float t   = __fdividef(a2 * copysignf(1.0f, dd), fabsf(dd) + u);     \
    const float c   = rsqrtf(fmaf(t, t, 1.0f));                                \
    const float s   = t * c;                                                   \
    W[sidx(p, p)] = fmaf(-t, apq, W[sidx(p, p)]);                              \
    W[sidx(q, q)] = fmaf( t, apq, W[sidx(q, q)]);                              \
    W[sidx(q, p)] = 0.0f;                                                      \
    _Pragma("unroll")                                                          \
    for (int k = 0; k < QC_DIM; k++) {                                         \
        if (k != p && k != q) {                                                \
            const float akp = W[symi(k, p)];                                   \
            const float akq = W[symi(k, q)];                                   \
            W[symi(k, p)] = fmaf(c, akp, -s * akq);                            \
            W[symi(k, q)] = fmaf(s, akp,  c * akq);                            \
        }                                                                      \
    }                                                                          \
} while (0)

__global__ void __launch_bounds__(32, 8)
qcbow_kernel(const int* __restrict__ contexts,
             float* __restrict__ out,
             int B) {
    const int e = blockIdx.x * blockDim.x + threadIdx.x;
    if (e >= B) return;

    // ---- cnt from context tokens (densities are already mask-weighted) ----
    float cnt = 0.f;
    {
        const int2* c2 = reinterpret_cast<const int2*>(contexts + e * QC_S);
#pragma unroll
        for (int v = 0; v < 5; v++) {
            const int2 t = c2[v];
            cnt += (t.x != 0) ? 1.f : 0.f;
            cnt += (t.y != 0) ? 1.f : 0.f;
        }
    }

    // ---- ctx = mean of 10 mask-weighted densities (coalesced reads) ----
    float ctx[QC_TRIL];
#pragma unroll
    for (int v = 0; v < 9; v++) {
        float4 a = g_scratch[(long)v * QC_B + e];           // slot 0
#pragma unroll
        for (int s = 1; s < QC_S; s++) {
            const float4 q = g_scratch[((long)s * 9 + v) * QC_B + e];
            a.x += q.x; a.y += q.y; a.z += q.z; a.w += q.w;
        }
        ctx[4 * v + 0] = a.x; ctx[4 * v + 1] = a.y;
        ctx[4 * v + 2] = a.z; ctx[4 * v + 3] = a.w;
    }
    {
        const float ic = __fdividef(1.0f, cnt);  // cnt==0 -> inf, matches ref 0/0
#pragma unroll
        for (int i = 0; i < QC_TRIL; i++) ctx[i] *= ic;
    }

    // ---- sigma from slot 10 (coalesced) ----
    float sig[QC_TRIL];
#pragma unroll
    for (int v = 0; v < 9; v++) {
        const float4 q = g_scratch[((long)QC_S * 9 + v) * QC_B + e];
        sig[4 * v + 0] = q.x; sig[4 * v + 1] = q.y;
        sig[4 * v + 2] = q.z; sig[4 * v + 3] = q.w;
    }

    // ---- in-place Cholesky of (ctx + 1e-6 I): ctx becomes C with C C^T ----
#pragma unroll
    for (int j = 0; j < QC_DIM; j++) {
        float d = ctx[sidx(j, j)] + 1e-6f;
#pragma unroll
        for (int k = 0; k < j; k++) d = fmaf(-ctx[sidx(j, k)], ctx[sidx(j, k)], d);
        d = fmaxf(d, 1e-14f);
        const float icjj = rsqrtf(d);
        ctx[sidx(j, j)] = d * icjj;
#pragma unroll
        for (int i = j + 1; i < QC_DIM; i++) {
            float v = ctx[sidx(i, j)];
#pragma unroll
            for (int k = 0; k < j; k++) v = fmaf(-ctx[sidx(i, k)], ctx[sidx(j, k)], v);
            ctx[sidx(i, j)] = v * icjj;
        }
    }

    // ---- W = C^T * sigma * C, packed lower-tri ----
    float W[QC_TRIL];
#pragma unroll
    for (int j = 0; j < QC_DIM; j++) {
        float tj[QC_DIM];  // column j of T = sigma * C
#pragma unroll
        for (int i = 0; i < QC_DIM; i++) {
            float s = 0.f;
#pragma unroll
            for (int k = j; k < QC_DIM; k++)      // C[k][j] nonzero for k>=j
                s = fmaf(sig[symi(i, k)], ctx[sidx(k, j)], s);
            tj[i] = s;
        }
#pragma unroll
        for (int i = 0; i <= j; i++) {
            float s = 0.f;
#pragma unroll
            for (int k = i; k < QC_DIM; k++)      // C[k][i] nonzero for k>=i
                s = fmaf(ctx[sidx(k, i)], tj[k], s);
            W[sidx(j, i)] = s;
        }
    }

    // ---- eigenvalues-only packed Jacobi, round-robin, 3 sweeps ----
#pragma unroll 1
    for (int sweep = 0; sweep < 3; sweep++) {
        JROT(0, 7); JROT(1, 6); JROT(2, 5); JROT(3, 4);
        JROT(1, 7); JROT(0, 2); JROT(3, 6); JROT(4, 5);
        JROT(2, 7); JROT(1, 3); JROT(0, 4); JROT(5, 6);
        JROT(3, 7); JROT(2, 4); JROT(1, 5); JROT(0, 6);
        JROT(4, 7); JROT(3, 5); JROT(2, 6); JROT(0, 1);
        JROT(5, 7); JROT(4, 6); JROT(0, 3); JROT(1, 2);
        JROT(6, 7); JROT(0, 5); JROT(1, 4); JROT(2, 3);
    }

    // ---- f = sum sqrt(|eig| + eps); out = -log(clip(f)) ----
    float f = 0.f;
#pragma unroll
    for (int i = 0; i < QC_DIM; i++) {
        const float x = fabsf(W[sidx(i, i)]) + 1e-6f;
        f = fmaf(x, rsqrtf(x), f);   // sqrt(x) = x * rsqrt(x), x >= 1e-6
    }
    f = fminf(f, 1.0f);
    f = fmaxf(f, 1e-8f);
    out[e] = -logf(f);
}

extern "C" void kernel_launch(void* const* d_in, const int* in_sizes, int n_in,
                              void* d_out, int out_size) {
    const int*   contexts = (const int*)d_in[0];   // [B, 10] int32
    const int*   targets  = (const int*)d_in[1];   // [B] int32
    const float* emb      = (const float*)d_in[2]; // [V, 36] float32
    float*       out      = (float*)d_out;         // [B] float32
    const int B = in_sizes[1];                     // 16384 (== QC_B)

    dim3 gA((B + 31) / 32, SLOTS);
    density_kernel<<<gA, 32>>>(contexts, targets, emb, B);
    qcbow_kernel<<<(B + 31) / 32, 32>>>(contexts, out, B);
}

// round 11
// speedup vs baseline: 1.4804x; 1.4804x over previous
#include <cuda_runtime.h>
#include <cuda_bf16.h>
#include <cuda_pipeline.h>

// QuantumCBOW: B=16384, S=10, DIM=8, TRIL=36.
// R11 = R9 (17.1us baseline: packed Jacobi, 3 sweeps, 512x32 launch) with ONE
// change: warp-cooperative async gather. All 352 embedding rows for the warp
// (11 slots x 32 lanes) are staged into smem up front via LDGSTS
// (__pipeline_memcpy_async): consecutive lanes fetch consecutive 16B chunks
// (~6 lines/instr vs ~32 for the divergent per-thread gather), all 99 copies
// in flight at once. Compute then reads conflict-free from smem.

#define QC_DIM  8
#define QC_TRIL 36
#define QC_S    10
#define SLOTS   11            // 10 context tokens + 1 target

__device__ __forceinline__ constexpr int sidx(int i, int j) { return i * (i + 1) / 2 + j; }
__device__ __forceinline__ constexpr int symi(int i, int j) { return (i >= j) ? sidx(i, j) : sidx(j, i); }

// Packed-symmetric branchless Jacobi rotation on W[36], pair (p,q), p<q.
#define JROT(p, q) do {                                                        \
    const float apq = W[sidx(q, p)];                                           \
    const float dd  = W[sidx(q, q)] - W[sidx(p, p)];                           \
    const float a2  = 2.0f * apq;                                              \
    const float vv  = fmaf(dd, dd, fmaf(a2, a2, 1e-30f));                      \
    const float u   = vv * rsqrtf(vv);                                         \
    const float t   = __fdividef(a2 * copysignf(1.0f, dd), fabsf(dd) + u);     \
    const float c   = rsqrtf(fmaf(t, t, 1.0f));                                \
    const float s   = t * c;                                                   \
    W[sidx(p, p)] = fmaf(-t, apq, W[sidx(p, p)]);                              \
    W[sidx(q, q)] = fmaf( t, apq, W[sidx(q, q)]);                              \
    W[sidx(q, p)] = 0.0f;                                                      \
    _Pragma("unroll")                                                          \
    for (int k = 0; k < QC_DIM; k++) {                                         \
        if (k != p && k != q) {                                                \
            const float akp = W[symi(k, p)];                                   \
            const float akq = W[symi(k, q)];                                   \
            W[symi(k, p)] = fmaf(c, akp, -s * akq);                            \
            W[symi(k, q)] = fmaf(s, akp,  c * akq);                            \
        }                                                                      \
    }                                                                          \
} while (0)

__global__ void __launch_bounds__(32, 4)
qcbow_kernel(const int* __restrict__ contexts,
             const int* __restrict__ targets,
             const float* __restrict__ emb,
             float* __restrict__ out,
             int B) {
    // Row r (= slot*32 + lane) chunk v lives at rows[r*9 + v].
    __shared__ float4 rows[SLOTS * 32 * 9];      // 50688 B
    __shared__ int    stok[SLOTS * 32];          // 1408 B

    const int lane = threadIdx.x;
    const int e = blockIdx.x * 32 + lane;
    const bool valid = (e < B);

    // ---- token ids (row is 8B-aligned: 10 ints = 5 x int2) ----
    int toks[QC_S];
    {
        const int eo = valid ? e : 0;
        const int2* c2 = reinterpret_cast<const int2*>(contexts + eo * QC_S);
#pragma unroll
        for (int v = 0; v < 5; v++) {
            const int2 t = c2[v];
            toks[2 * v] = t.x; toks[2 * v + 1] = t.y;
        }
        stok[QC_S * 32 + lane] = targets[eo];
    }
#pragma unroll
    for (int s = 0; s < QC_S; s++) stok[s * 32 + lane] = toks[s];
    __syncwarp();

    // ---- cooperative async gather: 352 rows x 9 chunks = 99 LDGSTS/lane ----
    const float4* emb4 = reinterpret_cast<const float4*>(emb);
#pragma unroll
    for (int i = 0; i < 99; i++) {               // 99*32 = 3168 = 352*9 exactly
        const int g = i * 32 + lane;
        const int r = g / 9;                     // row 0..351
        const int v = g - r * 9;                 // chunk 0..8
        const int tok = stok[r];
        __pipeline_memcpy_async(&rows[g], emb4 + tok * 9 + v, 16);
    }
    __pipeline_commit();
    __pipeline_wait_prior(0);
    __syncwarp();

    // ---- context rho: branchless masked mean over 10 slots (from smem) ----
    float ctx[QC_TRIL];
#pragma unroll
    for (int i = 0; i < QC_TRIL; i++) ctx[i] = 0.f;
    float cnt = 0.f;
#pragma unroll 2
    for (int s = 0; s < SLOTS; s++) {
        float* acc = (s == QC_S) ? nullptr : ctx;  // handled below
        float L[QC_TRIL];
        const float4* rp = rows + (s * 32 + lane) * 9;
#pragma unroll
        for (int v = 0; v < 9; v++) {
            const float4 q = rp[v];
            L[4 * v + 0] = q.x; L[4 * v + 1] = q.y;
            L[4 * v + 2] = q.z; L[4 * v + 3] = q.w;
        }
#pragma unroll
        for (int i = 0; i < QC_DIM; i++) {
            const int d = sidx(i, i);
            L[d] = fmaxf(L[d], 1e-4f);
        }
        float tr = 0.f;
#pragma unroll
        for (int i = 0; i < QC_TRIL; i++) tr = fmaf(L[i], L[i], tr);
        float m;
        if (s == QC_S) m = 1.0f;
        else { m = (toks[s] != 0) ? 1.0f : 0.0f; cnt += m; }
        const float inv = m * __fdividef(1.0f, tr + 1.7e-5f);
        // For context slots accumulate into ctx; the target slot is handled
        // after the loop (sigma) — so stash target result separately.
        if (s < QC_S) {
#pragma unroll
            for (int i = 0; i < QC_DIM; i++) {
#pragma unroll
                for (int j = 0; j <= i; j++) {
                    float a = 0.f;
#pragma unroll
                    for (int k = 0; k <= j; k++)
                        a = fmaf(L[sidx(i, k)], L[sidx(j, k)], a);
                    if (i == j) a += 2e-6f;
                    acc[sidx(i, j)] = fmaf(a, inv, acc[sidx(i, j)]);
                }
            }
        }
    }
    {
        const float ic = __fdividef(1.0f, cnt);  // cnt==0 -> inf, matches ref 0/0
#pragma unroll
        for (int i = 0; i < QC_TRIL; i++) ctx[i] *= ic;
    }

    // ---- in-place Cholesky of (ctx + 1e-6 I): ctx becomes C with C C^T ----
#pragma unroll
    for (int j = 0; j < QC_DIM; j++) {
        float d = ctx[sidx(j, j)] + 1e-6f;
#pragma unroll
        for (int k = 0; k < j; k++) d = fmaf(-ctx[sidx(j, k)], ctx[sidx(j, k)], d);
        d = fmaxf(d, 1e-14f);
        const float icjj = rsqrtf(d);
        ctx[sidx(j, j)] = d * icjj;
#pragma unroll
        for (int i = j + 1; i < QC_DIM; i++) {
            float v = ctx[sidx(i, j)];
#pragma unroll
            for (int k = 0; k < j; k++) v = fmaf(-ctx[sidx(i, k)], ctx[sidx(j, k)], v);
            ctx[sidx(i, j)] = v * icjj;
        }
    }

    // ---- target sigma (slot 10, from smem) ----
    float sig[QC_TRIL];
    {
        float L[QC_TRIL];
        const float4* rp = rows + (QC_S * 32 + lane) * 9;
#pragma unroll
        for (int v = 0; v < 9; v++) {
            const float4 q = rp[v];
            L[4 * v + 0] = q.x; L[4 * v + 1] = q.y;
            L[4 * v + 2] = q.z; L[4 * v + 3] = q.w;
        }
#pragma unroll
        for (int i = 0; i < QC_DIM; i++) {
            const int d = sidx(i, i);
            L[d] = fmaxf(L[d], 1e-4f);
        }
        float tr = 0.f;
#pragma unroll
        for (int i = 0; i < QC_TRIL; i++) tr = fmaf(L[i], L[i], tr);
        const float inv = __fdividef(1.0f, tr + 1.7e-5f);
#pragma unroll
        for (int i = 0; i < QC_DIM; i++) {
#pragma unroll
            for (int j = 0; j <= i; j++) {
                float a = 0.f;
#pragma unroll
                for (int k = 0; k <= j; k++)
                    a = fmaf(L[sidx(i, k)], L[sidx(j, k)], a);
                if (i == j) a += 2e-6f;
                sig[sidx(i, j)] = a * inv;
            }
        }
    }

    // ---- W = C^T * sigma * C, packed lower-tri ----
    float W[QC_TRIL];
#pragma unroll
    for (int j = 0; j < QC_DIM; j++) {
        float tj[QC_DIM];  // column j of T = sigma * C
#pragma unroll
        for (int i = 0; i < QC_DIM; i++) {
            float s = 0.f;
#pragma unroll
            for (int k = j; k < QC_DIM; k++)      // C[k][j] nonzero for k>=j
                s = fmaf(sig[symi(i, k)], ctx[sidx(k, j)], s);
            tj[i] = s;
        }
#pragma unroll
        for (int i = 0; i <= j; i++) {
            float s = 0.f;
#pragma unroll
            for (int k = i; k < QC_DIM; k++)      // C[k][i] nonzero for k>=i
                s = fmaf(ctx[sidx(k, i)], tj[k], s);
            W[sidx(j, i)] = s;
        }
    }

    // ---- eigenvalues-only packed Jacobi, round-robin, 3 sweeps ----
#pragma unroll 1
    for (int sweep = 0; sweep < 3; sweep++) {
        JROT(0, 7); JROT(1, 6); JROT(2, 5); JROT(3, 4);
        JROT(1, 7); JROT(0, 2); JROT(3, 6); JROT(4, 5);
        JROT(2, 7); JROT(1, 3); JROT(0, 4); JROT(5, 6);
        JROT(3, 7); JROT(2, 4); JROT(1, 5); JROT(0, 6);
        JROT(4, 7); JROT(3, 5); JROT(2, 6); JROT(0, 1);
        JROT(5, 7); JROT(4, 6); JROT(0, 3); JROT(1, 2);
        JROT(6, 7); JROT(0, 5); JROT(1, 4); JROT(2, 3);
    }

    // ---- f = sum sqrt(|eig| + eps); out = -log(clip(f)) ----
    float f = 0.f;
#pragma unroll
    for (int i = 0; i < QC_DIM; i++) {
        const float x = fabsf(W[sidx(i, i)]) + 1e-6f;
        f = fmaf(x, rsqrtf(x), f);   // sqrt(x) = x * rsqrt(x), x >= 1e-6
    }
    f = fminf(f, 1.0f);
    f = fmaxf(f, 1e-8f);
    if (valid) out[e] = -logf(f);
}

extern "C" void kernel_launch(void* const* d_in, const int* in_sizes, int n_in,
                              void* d_out, int out_size) {
    const int*   contexts = (const int*)d_in[0];   // [B, 10] int32
    const int*   targets  = (const int*)d_in[1];   // [B] int32
    const float* emb      = (const float*)d_in[2]; // [V, 36] float32
    float*       out      = (float*)d_out;         // [B] float32
    const int B = in_sizes[1];
    const int blocks = (B + 31) / 32;               // 512 blocks -> all 148 SMs busy
    qcbow_kernel<<<blocks, 32>>>(contexts, targets, emb, out, B);
}

// round 12
// speedup vs baseline: 1.5028x; 1.0152x over previous
#include <cuda_runtime.h>
#include <cuda_bf16.h>

// QuantumCBOW: B=16384, S=10, DIM=8, TRIL=36.
// R12: 2 lanes per element (32768 threads, 1024 warps = 1.73/SMSP) to escape
// the single-warp FFMA rt=2 cap that pinned R6/R9/R11 at 17.1us.
//  - lane h: 5 ctx densities + sigma density (x2 redundant; same issue cost
//    as divergence), 1-step butterfly for ctx
//  - lane h=0 Choleskys ctx->C, h=1 Choleskys sigma->S (uniform code, no
//    divergence); one 36-shfl factor exchange
//  - each lane owns 4 columns of A = S^T C; one-sided Jacobi with XOR-paired
//    cross rounds (compile-time shfl indices), snapshot-then-rotate;
//    rotation formula = R5-validated both-sides-consistent OS_ROT
//  - F = sum sqrt(colnorm^2(A) + eps)

#define QC_DIM  8
#define QC_TRIL 36
#define QC_S    10

__device__ __forceinline__ constexpr int sidx(int i, int j) { return i * (i + 1) / 2 + j; }

// Accumulate wgt * normalized-density(row) into acc[36] (lower-tri storage).
__device__ __forceinline__ void add_density(const float* __restrict__ row, float* acc, float wgt) {
    float L[QC_TRIL];
    const float4* r4 = reinterpret_cast<const float4*>(row);  // 36*4B rows, 16B aligned
#pragma unroll
    for (int v = 0; v < 9; v++) {
        float4 t = r4[v];
        L[4 * v + 0] = t.x; L[4 * v + 1] = t.y;
        L[4 * v + 2] = t.z; L[4 * v + 3] = t.w;
    }
#pragma unroll
    for (int i = 0; i < QC_DIM; i++) {
        const int d = sidx(i, i);
        L[d] = fmaxf(L[d], 1e-4f);
    }
    float tr = 0.f;
#pragma unroll
    for (int i = 0; i < QC_TRIL; i++) tr = fmaf(L[i], L[i], tr);
    const float inv = wgt * __fdividef(1.0f, tr + 1.7e-5f);
#pragma unroll
    for (int i = 0; i < QC_DIM; i++) {
#pragma unroll
        for (int j = 0; j <= i; j++) {
            float s = 0.f;
#pragma unroll
            for (int k = 0; k <= j; k++)
                s = fmaf(L[sidx(i, k)], L[sidx(j, k)], s);
            if (i == j) s += 2e-6f;  // eps + corr
            acc[sidx(i, j)] = fmaf(s, inv, acc[sidx(i, j)]);
        }
    }
}

// One-sided rotation of own column COL against partner snapshot P.
// Both lanes of a pair see (n, pn) swapped -> dd flips sign -> consistent
// updates (R5-validated).
#define OS_ROT(COL, P, n_, pn_) do {                                           \
    float g = 0.f;                                                             \
    _Pragma("unroll")                                                          \
    for (int k = 0; k < QC_DIM; k++) g = fmaf(COL[k], P[k], g);                \
    const float dd = (pn_) - (n_);                                             \
    const float a2 = 2.0f * g;                                                 \
    const float vv = fmaf(dd, dd, fmaf(a2, a2, 1e-30f));                       \
    const float u  = vv * rsqrtf(vv);                                          \
    const float t  = __fdividef(a2 * copysignf(1.0f, dd), fabsf(dd) + u);      \
    const float c  = rsqrtf(fmaf(t, t, 1.0f));                                 \
    const float s  = t * c;                                                    \
    _Pragma("unroll")                                                          \
    for (int k = 0; k < QC_DIM; k++)                                           \
        COL[k] = fmaf(c, COL[k], -s * P[k]);                                   \
    n_ = fmaf(-t, g, n_);                                                      \
} while (0)

// Local rotation of two own columns (full update, R5-validated).
#define OS_LOCAL(CA, CB, na, nb) do {                                          \
    float g = 0.f;                                                             \
    _Pragma("unroll")                                                          \
    for (int k = 0; k < QC_DIM; k++) g = fmaf(CA[k], CB[k], g);                \
    const float dd = (nb) - (na);                                              \
    const float a2 = 2.0f * g;                                                 \
    const float vv = fmaf(dd, dd, fmaf(a2, a2, 1e-30f));                       \
    const float u  = vv * rsqrtf(vv);                                          \
    const float t  = __fdividef(a2 * copysignf(1.0f, dd), fabsf(dd) + u);      \
    const float c  = rsqrtf(fmaf(t, t, 1.0f));                                 \
    const float s  = t * c;                                                    \
    _Pragma("unroll")                                                          \
    for (int k = 0; k < QC_DIM; k++) {                                         \
        const float x = CA[k], y = CB[k];                                      \
        CA[k] = fmaf(c, x, -s * y);                                            \
        CB[k] = fmaf(s, x,  c * y);                                            \
    }                                                                          \
    na = fmaf(-t, g, na);                                                      \
    nb = fmaf( t, g, nb);                                                      \
} while (0)

// Cross round x: own col c pairs with partner col c^x. Both lanes send a[c^x]
// and receive the partner's a[c^x] (symmetric, compile-time index). Snapshot
// all 4 partner cols + norms BEFORE any rotation (state consistency).
#define XROUND(x) do {                                                         \
    float p0[QC_DIM], p1[QC_DIM], p2[QC_DIM], p3[QC_DIM];                      \
    _Pragma("unroll")                                                          \
    for (int k = 0; k < QC_DIM; k++) {                                         \
        p0[k] = __shfl_xor_sync(0xffffffffu, a[0 ^ (x)][k], 1);                \
        p1[k] = __shfl_xor_sync(0xffffffffu, a[1 ^ (x)][k], 1);                \
        p2[k] = __shfl_xor_sync(0xffffffffu, a[2 ^ (x)][k], 1);                \
        p3[k] = __shfl_xor_sync(0xffffffffu, a[3 ^ (x)][k], 1);                \
    }                                                                          \
    const float q0 = __shfl_xor_sync(0xffffffffu, n[0 ^ (x)], 1);              \
    const float q1 = __shfl_xor_sync(0xffffffffu, n[1 ^ (x)], 1);              \
    const float q2 = __shfl_xor_sync(0xffffffffu, n[2 ^ (x)], 1);              \
    const float q3 = __shfl_xor_sync(0xffffffffu, n[3 ^ (x)], 1);              \
    OS_ROT(a[0], p0, n[0], q0);                                                \
    OS_ROT(a[1], p1, n[1], q1);                                                \
    OS_ROT(a[2], p2, n[2], q2);                                                \
    OS_ROT(a[3], p3, n[3], q3);                                                \
} while (0)

__global__ void __launch_bounds__(128, 2)
qcbow_kernel(const int* __restrict__ contexts,
             const int* __restrict__ targets,
             const float* __restrict__ emb,
             float* __restrict__ out,
             int B) {
    const int gt = blockIdx.x * 128 + threadIdx.x;
    const int e = gt >> 1;
    const int h = gt & 1;
    if (e >= B) return;   // B even and 2B % 128 == 0 -> no partial pairs/warps

    // ---- token ids (row is 8B-aligned: 10 ints = 5 x int2) ----
    int toks[QC_S];
    {
        const int2* c2 = reinterpret_cast<const int2*>(contexts + e * QC_S);
#pragma unroll
        for (int v = 0; v < 5; v++) {
            const int2 t = c2[v];
            toks[2 * v] = t.x; toks[2 * v + 1] = t.y;
        }
    }
    const int tgt = targets[e];

    // ---- sigma density (both lanes; same row -> L1 broadcast) ----
    float sigm[QC_TRIL];
#pragma unroll
    for (int i = 0; i < QC_TRIL; i++) sigm[i] = 0.f;
    add_density(emb + (long)tgt * QC_TRIL, sigm, 1.0f);

    // ---- 5 context densities for this lane: tokens {2k + h} ----
    float ctxp[QC_TRIL];
#pragma unroll
    for (int i = 0; i < QC_TRIL; i++) ctxp[i] = 0.f;
    float cnt = 0.f;
#pragma unroll
    for (int k = 0; k < 5; k++) {
        const int tok = toks[2 * k + h];
        const float m = (tok != 0) ? 1.0f : 0.0f;
        cnt += m;
        add_density(emb + (long)tok * QC_TRIL, ctxp, m);
    }

    // ---- butterfly: full ctx + cnt across the lane pair ----
    cnt += __shfl_xor_sync(0xffffffffu, cnt, 1);
#pragma unroll
    for (int i = 0; i < QC_TRIL; i++)
        ctxp[i] += __shfl_xor_sync(0xffffffffu, ctxp[i], 1);
    const float ic = __fdividef(1.0f, cnt);  // cnt==0 -> inf, matches ref 0/0

    // ---- my Cholesky target: h0 -> ctx/cnt + 1e-6 I, h1 -> sigma ----
    float mat[QC_TRIL];
#pragma unroll
    for (int i = 0; i < QC_TRIL; i++) {
        const float cv = ctxp[i] * ic;
        mat[i] = h ? sigm[i] : cv;
    }
    const float dadd = h ? 0.0f : 1e-6f;
#pragma unroll
    for (int d = 0; d < QC_DIM; d++) mat[sidx(d, d)] += dadd;

    // ---- in-place Cholesky of mat (uniform code, per-lane data) ----
#pragma unroll
    for (int j = 0; j < QC_DIM; j++) {
        float d = mat[sidx(j, j)];
#pragma unroll
        for (int k = 0; k < j; k++) d = fmaf(-mat[sidx(j, k)], mat[sidx(j, k)], d);
        d = fmaxf(d, 1e-20f);
        const float icjj = rsqrtf(d);
        mat[sidx(j, j)] = d * icjj;
#pragma unroll
        for (int i = j + 1; i < QC_DIM; i++) {
            float v = mat[sidx(i, j)];
#pragma unroll
            for (int k = 0; k < j; k++) v = fmaf(-mat[sidx(i, k)], mat[sidx(j, k)], v);
            mat[sidx(i, j)] = v * icjj;
        }
    }
    // h0: mat = C (CC^T = ctx+1e-6I); h1: mat = S (SS^T = sigma)

    // ---- factor exchange: oth = partner's factor ----
    float oth[QC_TRIL];
#pragma unroll
    for (int i = 0; i < QC_TRIL; i++)
        oth[i] = __shfl_xor_sync(0xffffffffu, mat[i], 1);
    // h0: C=mat, S=oth;  h1: S=mat, C=oth

    // ---- my 4 columns of A = S^T C  (cols 4h .. 4h+3) ----
    float Cc[4][QC_DIM];       // C[k][4h+jj], zero-padded k<col
#pragma unroll
    for (int jj = 0; jj < 4; jj++) {
#pragma unroll
        for (int k = 0; k < QC_DIM; k++) {
            const float v0 = (k >= jj)     ? mat[(k >= jj)     ? sidx(k, jj)     : 0] : 0.f;
            const float v1 = (k >= jj + 4) ? oth[(k >= jj + 4) ? sidx(k, jj + 4) : 0] : 0.f;
            Cc[jj][k] = h ? v1 : v0;
        }
    }
    float a[4][QC_DIM];        // a[jj][i] = A[i][4h+jj]
#pragma unroll
    for (int jj = 0; jj < 4; jj++)
#pragma unroll
        for (int i = 0; i < QC_DIM; i++) a[jj][i] = 0.f;
#pragma unroll
    for (int i = 0; i < QC_DIM; i++) {
#pragma unroll
        for (int k = i; k < QC_DIM; k++) {
            const float sv = h ? mat[sidx(k, i)] : oth[sidx(k, i)];   // S[k][i]
#pragma unroll
            for (int jj = 0; jj < 4; jj++)
                a[jj][i] = fmaf(sv, Cc[jj][k], a[jj][i]);
        }
    }

    // ---- one-sided Jacobi: 3 sweeps x (3 local + 4 cross) rounds ----
    float n[4];
#pragma unroll 1
    for (int sweep = 0; sweep < 3; sweep++) {
        // fresh norms each sweep
#pragma unroll
        for (int jj = 0; jj < 4; jj++) {
            float s = 0.f;
#pragma unroll
            for (int k = 0; k < QC_DIM; k++) s = fmaf(a[jj][k], a[jj][k], s);
            n[jj] = s;
        }
        OS_LOCAL(a[0], a[1], n[0], n[1]); OS_LOCAL(a[2], a[3], n[2], n[3]);
        OS_LOCAL(a[0], a[2], n[0], n[2]); OS_LOCAL(a[1], a[3], n[1], n[3]);
        OS_LOCAL(a[0], a[3], n[0], n[3]); OS_LOCAL(a[1], a[2], n[1], n[2]);
        XROUND(0); XROUND(1); XROUND(2); XROUND(3);
    }

    // ---- f = sum sqrt(colnorm^2 + eps) over all 8 cols ----
    float p = 0.f;
#pragma unroll
    for (int jj = 0; jj < 4; jj++) {
        float s = 0.f;
#pragma unroll
        for (int k = 0; k < QC_DIM; k++) s = fmaf(a[jj][k], a[jj][k], s);
        const float x = s + 1e-6f;
        p = fmaf(x, rsqrtf(x), p);   // sqrt(x) = x*rsqrt(x)
    }
    p += __shfl_xor_sync(0xffffffffu, p, 1);
    if (h == 0) {
        float f = fminf(p, 1.0f);
        f = fmaxf(f, 1e-8f);
        out[e] = -logf(f);
    }
}

extern "C" void kernel_launch(void* const* d_in, const int* in_sizes, int n_in,
                              void* d_out, int out_size) {
    const int*   contexts = (const int*)d_in[0];   // [B, 10] int32
    const int*   targets  = (const int*)d_in[1];   // [B] int32
    const float* emb      = (const float*)d_in[2]; // [V, 36] float32
    float*       out      = (float*)d_out;         // [B] float32
    const int B = in_sizes[1];                     // 16384
    const int threads = 128;
    const int blocks = (2 * B + threads - 1) / threads;   // 256 blocks
    qcbow_kernel<<<blocks, threads>>>(contexts, targets, emb, out, B);
}